// round 1
// baseline (speedup 1.0000x reference)
#include <cuda_runtime.h>

// Problem constants
#define BB 64
#define NN 8192
#define CC 80
#define MM 300
#define SS (64 * 300)   // 19200 selected entries

#define RANK_THREADS 128
#define CHUNK (SS / RANK_THREADS)   // 150 (exact)

// Output layout (floats): num_pred[64] | det_boxes[64*300*4] | det_scores[64*300] | det_classes[64*300]
#define OFF_BOXES   (BB)                       // 64
#define OFF_SCORES  (BB + BB * MM * 4)         // 76864
#define OFF_CLASSES (BB + BB * MM * 5)         // 96064
#define OUT_FLOATS  (BB + BB * MM * 6)         // 115264

// Scratch: stable slot per selected entry (-1 = dropped)
__device__ int g_slot[SS];

// ---------------------------------------------------------------------------
// K1: zero the whole output (float4 stores; OUT_FLOATS % 4 == 0)
// ---------------------------------------------------------------------------
__global__ void zero_kernel(float4* __restrict__ out4) {
    int i = blockIdx.x * blockDim.x + threadIdx.x;
    if (i < OUT_FLOATS / 4) out4[i] = make_float4(0.f, 0.f, 0.f, 0.f);
}

// ---------------------------------------------------------------------------
// K2: stable per-batch rank. Single block, 128 threads.
//   hist laid out [thread][batch] so the prefix pass (thread b reads
//   hist[k][b] for all k) is bank-conflict-free across the warp.
// ---------------------------------------------------------------------------
__global__ void __launch_bounds__(RANK_THREADS, 1)
rank_kernel(const int* __restrict__ sel, float* __restrict__ out) {
    __shared__ int hist[RANK_THREADS][BB];   // 32 KB

    const int t = threadIdx.x;
    const int base = t * CHUNK;

    #pragma unroll
    for (int b = 0; b < BB; b++) hist[t][b] = 0;
    __syncthreads();

    // Phase 1: per-thread histogram over its contiguous (order-preserving) chunk
    for (int i = 0; i < CHUNK; i++) {
        int b = sel[(base + i) * 3];
        hist[t][b]++;
    }
    __syncthreads();

    // Phase 2: exclusive prefix across thread columns, per batch
    if (t < BB) {
        int run = 0;
        #pragma unroll
        for (int k = 0; k < RANK_THREADS; k++) {
            int c = hist[k][t];
            hist[k][t] = run;
            run += c;
        }
        out[t] = (float)run;   // num_predictions[b] (unclamped count)
    }
    __syncthreads();

    // Phase 3: assign stable slots
    for (int i = 0; i < CHUNK; i++) {
        int s = base + i;
        int b = sel[s * 3];
        int r = hist[t][b]++;                 // thread t owns row t: no atomics needed
        g_slot[s] = (r < MM) ? (b * MM + r) : -1;
    }
}

// ---------------------------------------------------------------------------
// K3: parallel gather + scatter, one thread per selected entry
// ---------------------------------------------------------------------------
__global__ void scatter_kernel(const float4* __restrict__ boxes4,   // [B*N] float4
                               const float* __restrict__ scores,    // [B*N*C]
                               const int* __restrict__ sel,         // [S*3]
                               float* __restrict__ out) {
    int s = blockIdx.x * blockDim.x + threadIdx.x;
    if (s >= SS) return;
    int slot = g_slot[s];
    if (slot < 0) return;

    int b   = sel[s * 3 + 0];
    int lab = sel[s * 3 + 1];
    int box = sel[s * 3 + 2];

    float4 bx = boxes4[b * NN + box];
    float  sc = scores[(b * NN + box) * CC + lab];

    // det_boxes: base offset 64 floats = 16 float4s, stays 16B-aligned
    float4* det_boxes = reinterpret_cast<float4*>(out + OFF_BOXES);
    det_boxes[slot]        = bx;
    out[OFF_SCORES + slot]  = sc;
    out[OFF_CLASSES + slot] = (float)lab;
}

// ---------------------------------------------------------------------------
// Launch
// ---------------------------------------------------------------------------
extern "C" void kernel_launch(void* const* d_in, const int* in_sizes, int n_in,
                              void* d_out, int out_size) {
    const float4* boxes4 = (const float4*)d_in[0];   // pred_boxes  (B,N,4) f32
    const float*  scores = (const float*)d_in[1];    // pred_scores (B,N,C) f32
    const int*    sel    = (const int*)d_in[2];      // selected_indexes (S,3) i32
    float* out = (float*)d_out;

    // K1: zero output
    {
        int n4 = OUT_FLOATS / 4;                     // 28816
        int threads = 256;
        int blocks = (n4 + threads - 1) / threads;   // 113
        zero_kernel<<<blocks, threads>>>((float4*)out);
    }

    // K2: stable ranks + num_predictions
    rank_kernel<<<1, RANK_THREADS>>>(sel, out);

    // K3: gather + scatter
    {
        int threads = 256;
        int blocks = (SS + threads - 1) / threads;   // 75
        scatter_kernel<<<blocks, threads>>>(boxes4, scores, sel, out);
    }
}

// round 4
// speedup vs baseline: 2.6923x; 2.6923x over previous
#include <cuda_runtime.h>

// Problem constants
#define BB 64
#define NN 8192
#define CC 80
#define MM 300
#define SS (64 * 300)          // 19200 selected entries
#define NBLK 75                // 75 * 256 == 19200 exactly
#define NWARP 8                // warps per block

// Output layout (floats): num_pred[64] | det_boxes[64*300*4] | det_scores[64*300] | det_classes[64*300]
#define OFF_BOXES   (BB)                       // 64
#define OFF_SCORES  (BB + BB * MM * 4)         // 76864
#define OFF_CLASSES (BB + BB * MM * 5)         // 96064
#define OUT_FLOATS  (BB + BB * MM * 6)         // 115264

// Scratch
__device__ int g_bhist[NBLK * BB];                 // per-block per-batch counts
__device__ unsigned long long g_pack[SS];          // packed {box,lab,b,lrank} per entry

// pack layout: bits [0,13) box | [13,20) lab | [20,26) b | [26,34) lrank
__device__ __forceinline__ unsigned long long pack_entry(int box, int lab, int b, int lrank) {
    return (unsigned long long)(unsigned)box
         | ((unsigned long long)(unsigned)lab   << 13)
         | ((unsigned long long)(unsigned)b     << 20)
         | ((unsigned long long)(unsigned)lrank << 26);
}

// ---------------------------------------------------------------------------
// K_A: zero output + within-block stable ranks + block histograms
// ---------------------------------------------------------------------------
__global__ void __launch_bounds__(256, 1)
rankA_kernel(const int* __restrict__ sel, float4* __restrict__ out4) {
    __shared__ int whist[NWARP][BB];   // 2 KB

    const int tid = threadIdx.x;
    const int blk = blockIdx.x;
    const int s   = blk * 256 + tid;

    // Kick off the index loads early (independent of the zeroing below)
    const int b   = sel[3 * s + 0];
    const int lab = sel[3 * s + 1];
    const int box = sel[3 * s + 2];

    // Zero the output (grid-stride over 28816 float4s; ~2 iters/thread).
    for (int i = blk * 256 + tid; i < OUT_FLOATS / 4; i += NBLK * 256)
        out4[i] = make_float4(0.f, 0.f, 0.f, 0.f);

    // Zero warp histograms
    for (int i = tid; i < NWARP * BB; i += 256)
        ((int*)whist)[i] = 0;
    __syncthreads();

    const int lane = tid & 31;
    const int w    = tid >> 5;
    const unsigned lt_mask = (1u << lane) - 1u;

    // Stable within-warp rank: lane order == entry order
    unsigned grp = __match_any_sync(0xffffffffu, b);
    int wrank  = __popc(grp & lt_mask);
    int leader = __ffs(grp) - 1;
    if (lane == leader)
        whist[w][b] = __popc(grp);      // one leader per (warp, b): plain store
    __syncthreads();

    // Exclusive prefix over the 8 warps, per batch; totals -> global
    if (tid < BB) {
        int run = 0;
        #pragma unroll
        for (int k = 0; k < NWARP; k++) {
            int c = whist[k][tid];
            whist[k][tid] = run;
            run += c;
        }
        g_bhist[blk * BB + tid] = run;
    }
    __syncthreads();

    g_pack[s] = pack_entry(box, lab, b, whist[w][b] + wrank);
}

// ---------------------------------------------------------------------------
// K_C: per-block prefix (redundant, smem) + final rank + gather + scatter.
//   Last block also writes num_predictions.
// ---------------------------------------------------------------------------
__global__ void __launch_bounds__(256, 1)
scatter_kernel(const float4* __restrict__ boxes4,   // [B*N] float4
               const float* __restrict__ scores,    // [B*N*C]
               float* __restrict__ out) {
    __shared__ int sh[NBLK * BB];      // 18.75 KB — full block histogram
    __shared__ int boff_sh[BB];

    const int tid = threadIdx.x;
    const int blk = blockIdx.x;
    const int s   = blk * 256 + tid;

    // Issue the packed-entry load first (independent of the smem staging)
    unsigned long long p = g_pack[s];

    // Stage full histogram into smem (L2-resident after the first block)
    for (int i = tid; i < NBLK * BB; i += 256)
        sh[i] = g_bhist[i];
    __syncthreads();

    // 64 threads: exclusive prefix for this block, per batch column
    if (tid < BB) {
        int run = 0;
        for (int k = 0; k < blk; k++)
            run += sh[k * BB + tid];
        boff_sh[tid] = run;
        // Last block finishes the scan -> per-batch totals = num_predictions
        if (blk == NBLK - 1) {
            #pragma unroll 5
            for (int k = blk; k < NBLK; k++)
                run += sh[k * BB + tid];
            out[tid] = (float)run;
        }
    }
    __syncthreads();

    int box   = (int)( p         & 0x1FFFu);
    int lab   = (int)((p >> 13)  & 0x7Fu);
    int b     = (int)((p >> 20)  & 0x3Fu);
    int lrank = (int)((p >> 26)  & 0xFFu);

    int r = boff_sh[b] + lrank;
    if (r >= MM) return;

    float4 bx = boxes4[b * NN + box];
    float  sc = scores[(b * NN + box) * CC + lab];

    int slot = b * MM + r;
    float4* det_boxes = reinterpret_cast<float4*>(out + OFF_BOXES);  // 16B-aligned (64 floats in)
    det_boxes[slot]         = bx;
    out[OFF_SCORES + slot]  = sc;
    out[OFF_CLASSES + slot] = (float)lab;
}

// ---------------------------------------------------------------------------
// Launch
// ---------------------------------------------------------------------------
extern "C" void kernel_launch(void* const* d_in, const int* in_sizes, int n_in,
                              void* d_out, int out_size) {
    const float4* boxes4 = (const float4*)d_in[0];   // pred_boxes  (B,N,4) f32
    const float*  scores = (const float*)d_in[1];    // pred_scores (B,N,C) f32
    const int*    sel    = (const int*)d_in[2];      // selected_indexes (S,3) i32
    float* out = (float*)d_out;

    rankA_kernel<<<NBLK, 256>>>(sel, (float4*)out);
    scatter_kernel<<<NBLK, 256>>>(boxes4, scores, out);
}

// round 5
// speedup vs baseline: 3.2609x; 1.2112x over previous
#include <cuda_runtime.h>

// Problem constants
#define BB 64
#define NN 8192
#define CC 80
#define MM 300
#define SS (64 * 300)          // 19200 selected entries
#define NBLK 150               // 150 * 128 == 19200 exactly; all resident (2/SM max)
#define NT 128
#define NWARP 4                // warps per block

// Output layout (floats): num_pred[64] | det_boxes[64*300*4] | det_scores[64*300] | det_classes[64*300]
#define OFF_BOXES   (BB)                       // 64
#define OFF_SCORES  (BB + BB * MM * 4)         // 76864
#define OFF_CLASSES (BB + BB * MM * 5)         // 96064
#define OUT_FLOATS  (BB + BB * MM * 6)         // 115264

// Scratch
__device__ int g_bhist[NBLK * BB];     // per-block per-batch counts
__device__ unsigned g_arrive;          // grid-barrier arrival counter (generation-counting,
                                       // never reset: works across graph replays)

// ---------------------------------------------------------------------------
// Fused kernel: zero + stable rank + grid barrier + prefix + gather/scatter
// ---------------------------------------------------------------------------
__global__ void __launch_bounds__(NT)
fused_kernel(const int* __restrict__ sel,        // [S*3]
             const float4* __restrict__ boxes4,  // [B*N] float4
             const float* __restrict__ scores,   // [B*N*C]
             float* __restrict__ out) {
    __shared__ int whist[NWARP][BB];   // 1 KB
    __shared__ int sh[NBLK * BB];      // 37.5 KB — staged block histograms
    __shared__ int boff_sh[BB];

    const int tid = threadIdx.x;
    const int blk = blockIdx.x;
    const int s   = blk * NT + tid;

    // ---- Phase 1: index loads (early), output zeroing, stable within-block rank
    const int b   = sel[3 * s + 0];
    const int lab = sel[3 * s + 1];
    const int box = sel[3 * s + 2];

    // Zero entire output: 28816 float4s over 19200 threads (<=2 iters)
    float4* out4 = reinterpret_cast<float4*>(out);
    for (int i = s; i < OUT_FLOATS / 4; i += NBLK * NT)
        out4[i] = make_float4(0.f, 0.f, 0.f, 0.f);

    for (int i = tid; i < NWARP * BB; i += NT)
        ((int*)whist)[i] = 0;
    __syncthreads();

    const int lane = tid & 31;
    const int w    = tid >> 5;
    const unsigned lt_mask = (1u << lane) - 1u;

    // Stable within-warp rank (lane order == entry order)
    unsigned grp = __match_any_sync(0xffffffffu, b);
    int wrank  = __popc(grp & lt_mask);
    int leader = __ffs(grp) - 1;
    if (lane == leader)
        whist[w][b] = __popc(grp);
    __syncthreads();

    // Exclusive prefix over the 4 warps per batch; block totals -> global
    if (tid < BB) {
        int run = 0;
        #pragma unroll
        for (int k = 0; k < NWARP; k++) {
            int c = whist[k][tid];
            whist[k][tid] = run;
            run += c;
        }
        g_bhist[blk * BB + tid] = run;
    }
    __syncthreads();

    const int lrank = whist[w][b] + wrank;   // within-block stable rank (register)

    // ---- Grid barrier (generation counting; no reset needed across replays)
    if (tid == 0) {
        __threadfence();                                  // release g_bhist + zero-stores
        unsigned old = atomicAdd(&g_arrive, 1u);
        unsigned target = (old / NBLK + 1u) * NBLK;
        while (atomicAdd(&g_arrive, 0u) < target) { }     // spin
    }
    __syncthreads();
    __threadfence();                                      // acquire

    // ---- Phase 2: stage histogram rows [0, blk) (last block stages all), scan
    {
        const int rows = (blk == NBLK - 1) ? NBLK : blk;
        const int n4 = rows * (BB / 4);
        const int4* src = reinterpret_cast<const int4*>(g_bhist);
        int4* dst = reinterpret_cast<int4*>(sh);
        for (int i = tid; i < n4; i += NT)
            dst[i] = src[i];
    }
    __syncthreads();

    if (tid < BB) {
        int run = 0;
        for (int k = 0; k < blk; k++)
            run += sh[k * BB + tid];
        boff_sh[tid] = run;
        if (blk == NBLK - 1) {                 // finish the scan -> num_predictions
            for (int k = blk; k < NBLK; k++)
                run += sh[k * BB + tid];
            out[tid] = (float)run;
        }
    }
    __syncthreads();

    // ---- Final rank, gather, scatter
    int r = boff_sh[b] + lrank;
    if (r >= MM) return;

    float4 bx = boxes4[b * NN + box];
    float  sc = scores[(b * NN + box) * CC + lab];

    int slot = b * MM + r;
    float4* det_boxes = reinterpret_cast<float4*>(out + OFF_BOXES);  // 16B-aligned
    det_boxes[slot]         = bx;
    out[OFF_SCORES + slot]  = sc;
    out[OFF_CLASSES + slot] = (float)lab;
}

// ---------------------------------------------------------------------------
// Launch
// ---------------------------------------------------------------------------
extern "C" void kernel_launch(void* const* d_in, const int* in_sizes, int n_in,
                              void* d_out, int out_size) {
    const float4* boxes4 = (const float4*)d_in[0];   // pred_boxes  (B,N,4) f32
    const float*  scores = (const float*)d_in[1];    // pred_scores (B,N,C) f32
    const int*    sel    = (const int*)d_in[2];      // selected_indexes (S,3) i32
    float* out = (float*)d_out;

    fused_kernel<<<NBLK, NT>>>(sel, boxes4, scores, out);
}

// round 6
// speedup vs baseline: 3.2710x; 1.0031x over previous
#include <cuda_runtime.h>

// Problem constants
#define BB 64
#define NN 8192
#define CC 80
#define MM 300
#define SS (64 * 300)          // 19200 selected entries
#define NBLK 150               // 150 * 128 == 19200 exactly; all resident (2/SM max)
#define NT 128
#define NWARP 4                // warps per block

// Output layout (floats): num_pred[64] | det_boxes[64*300*4] | det_scores[64*300] | det_classes[64*300]
#define OFF_BOXES   (BB)                       // 64
#define OFF_SCORES  (BB + BB * MM * 4)         // 76864
#define OFF_CLASSES (BB + BB * MM * 5)         // 96064
#define OUT_FLOATS  (BB + BB * MM * 6)         // 115264

// Scratch
__device__ int g_bhist[NBLK * BB];     // per-block per-batch counts
__device__ unsigned g_arrive;          // grid-barrier arrival counter (generation-counting,
                                       // never reset: works across graph replays)

// ---------------------------------------------------------------------------
// Fused kernel: zero + stable rank + grid barrier + prefix + gather/scatter
// ---------------------------------------------------------------------------
__global__ void __launch_bounds__(NT)
fused_kernel(const int* __restrict__ sel,        // [S*3]
             const float4* __restrict__ boxes4,  // [B*N] float4
             const float* __restrict__ scores,   // [B*N*C]
             float* __restrict__ out) {
    __shared__ int whist[NWARP][BB];   // 1 KB
    __shared__ int sh[NBLK * BB];      // 37.5 KB — staged block histograms
    __shared__ int boff_sh[BB];

    const int tid = threadIdx.x;
    const int blk = blockIdx.x;
    const int s   = blk * NT + tid;

    // ---- Phase 1: index loads (early), output zeroing, stable within-block rank
    const int b   = sel[3 * s + 0];
    const int lab = sel[3 * s + 1];
    const int box = sel[3 * s + 2];

    // Zero entire output: 28816 float4s over 19200 threads (<=2 iters)
    float4* out4 = reinterpret_cast<float4*>(out);
    for (int i = s; i < OUT_FLOATS / 4; i += NBLK * NT)
        out4[i] = make_float4(0.f, 0.f, 0.f, 0.f);

    for (int i = tid; i < NWARP * BB; i += NT)
        ((int*)whist)[i] = 0;
    __syncthreads();

    const int lane = tid & 31;
    const int w    = tid >> 5;
    const unsigned lt_mask = (1u << lane) - 1u;

    // Stable within-warp rank (lane order == entry order)
    unsigned grp = __match_any_sync(0xffffffffu, b);
    int wrank  = __popc(grp & lt_mask);
    int leader = __ffs(grp) - 1;
    if (lane == leader)
        whist[w][b] = __popc(grp);
    __syncthreads();

    // Exclusive prefix over the 4 warps per batch; block totals -> global
    if (tid < BB) {
        int run = 0;
        #pragma unroll
        for (int k = 0; k < NWARP; k++) {
            int c = whist[k][tid];
            whist[k][tid] = run;
            run += c;
        }
        g_bhist[blk * BB + tid] = run;
    }
    __syncthreads();

    const int lrank = whist[w][b] + wrank;   // within-block stable rank (register)

    // ---- Grid barrier (generation counting; no reset needed across replays)
    if (tid == 0) {
        __threadfence();                                  // release g_bhist + zero-stores
        unsigned old = atomicAdd(&g_arrive, 1u);
        unsigned target = (old / NBLK + 1u) * NBLK;
        while (atomicAdd(&g_arrive, 0u) < target) { }     // spin
    }
    __syncthreads();
    __threadfence();                                      // acquire

    // ---- Phase 2: stage histogram rows [0, blk) (last block stages all), scan
    {
        const int rows = (blk == NBLK - 1) ? NBLK : blk;
        const int n4 = rows * (BB / 4);
        const int4* src = reinterpret_cast<const int4*>(g_bhist);
        int4* dst = reinterpret_cast<int4*>(sh);
        for (int i = tid; i < n4; i += NT)
            dst[i] = src[i];
    }
    __syncthreads();

    if (tid < BB) {
        int run = 0;
        for (int k = 0; k < blk; k++)
            run += sh[k * BB + tid];
        boff_sh[tid] = run;
        if (blk == NBLK - 1) {                 // finish the scan -> num_predictions
            for (int k = blk; k < NBLK; k++)
                run += sh[k * BB + tid];
            out[tid] = (float)run;
        }
    }
    __syncthreads();

    // ---- Final rank, gather, scatter
    int r = boff_sh[b] + lrank;
    if (r >= MM) return;

    float4 bx = boxes4[b * NN + box];
    float  sc = scores[(b * NN + box) * CC + lab];

    int slot = b * MM + r;
    float4* det_boxes = reinterpret_cast<float4*>(out + OFF_BOXES);  // 16B-aligned
    det_boxes[slot]         = bx;
    out[OFF_SCORES + slot]  = sc;
    out[OFF_CLASSES + slot] = (float)lab;
}

// ---------------------------------------------------------------------------
// Launch
// ---------------------------------------------------------------------------
extern "C" void kernel_launch(void* const* d_in, const int* in_sizes, int n_in,
                              void* d_out, int out_size) {
    const float4* boxes4 = (const float4*)d_in[0];   // pred_boxes  (B,N,4) f32
    const float*  scores = (const float*)d_in[1];    // pred_scores (B,N,C) f32
    const int*    sel    = (const int*)d_in[2];      // selected_indexes (S,3) i32
    float* out = (float*)d_out;

    fused_kernel<<<NBLK, NT>>>(sel, boxes4, scores, out);
}